// round 10
// baseline (speedup 1.0000x reference)
#include <cuda_runtime.h>
#include <cstdint>

// Problem constants
#define S   8192
#define Dm  2048
#define E   64
#define CAP 128   // ceil(S/E * 1.0)

#define GATE_BLOCKS (S / 64)   // 128 blocks, one per SM
#define STAGES 4               // cp.async pipeline depth (3 tiles of slack)
#define RS 20                  // smem row stride in floats (80B: 16B-aligned, conflict-light)

// ---------------- device scratch (no allocations allowed) ----------------
__device__ int   g_expert[S];
__device__ float g_gate[S];
__device__ int   g_rank[S];
__device__ int   g_chunkHist[64 * 64];
__device__ int   g_chunkBase[64 * 64];
__device__ float g_partSum[GATE_BLOCKS * 64];

__device__ __forceinline__ void cpa16(uint32_t dst, const float* src) {
    asm volatile("cp.async.cg.shared.global [%0], [%1], 16;" :: "r"(dst), "l"(src));
}

// ---------------------------------------------------------------------------
// Kernel 1: logits = x @ wg^T. 64 tokens x 64 experts per 256-thread block,
// 4x4 register tile, 4-stage cp.async pipeline (prefetch distance 3 tiles
// ~3072 cyc) so the mainloop tolerates DRAM latency inflated by the
// concurrently-running 537MB output zero-fill. FFMA-bound at ~1024 cyc/tile.
// ---------------------------------------------------------------------------
__global__ __launch_bounds__(256, 1) void gate_kernel(const float* __restrict__ x,
                                                      const float* __restrict__ wg) {
    __shared__ __align__(16) float xs[STAGES][64][RS];  // [stage][token][k] row-major
    __shared__ __align__(16) float ws[STAGES][64][RS];  // [stage][expert][k]
    __shared__ float colv[16][64];

    const int tid = threadIdx.x;
    const int ty  = tid >> 4;      // 0..15 -> token quad
    const int tx  = tid & 15;      // 0..15 -> expert quad
    const int sb  = blockIdx.x * 64;

    float acc[4][4];
#pragma unroll
    for (int i = 0; i < 4; i++)
#pragma unroll
        for (int j = 0; j < 4; j++) acc[i][j] = 0.0f;

    // copy assignments: one 16B chunk of x and one of wg per thread per tile
    const int row = tid >> 2;          // token / expert 0..63
    const int kq  = (tid & 3) * 4;     // k offset within tile (float4)

    const float* xsrc = x  + (size_t)(sb + row) * Dm + kq;
    const float* wsrc = wg + (size_t)row * Dm + kq;

    uint32_t xdst[STAGES], wdst[STAGES];
#pragma unroll
    for (int p = 0; p < STAGES; p++) {
        xdst[p] = (uint32_t)__cvta_generic_to_shared(&xs[p][row][kq]);
        wdst[p] = (uint32_t)__cvta_generic_to_shared(&ws[p][row][kq]);
    }

    const int NT = Dm / 16;  // 128 k-tiles

    // prologue: fill stages 0..2
#pragma unroll
    for (int p = 0; p < STAGES - 1; p++) {
        cpa16(xdst[p], xsrc + p * 16);
        cpa16(wdst[p], wsrc + p * 16);
        asm volatile("cp.async.commit_group;");
    }

    for (int t = 0; t < NT; t++) {
        const int st = t & (STAGES - 1);
        // issue tile t+3 into the stage freed at end of iter t-1
        if (t + STAGES - 1 < NT) {
            const int pf = (t + STAGES - 1) & (STAGES - 1);
            cpa16(xdst[pf], xsrc + (t + STAGES - 1) * 16);
            cpa16(wdst[pf], wsrc + (t + STAGES - 1) * 16);
        }
        asm volatile("cp.async.commit_group;");       // uniform group count (empty ok)
        asm volatile("cp.async.wait_group 3;");       // oldest group (tile t) complete
        __syncthreads();

#pragma unroll
        for (int kk = 0; kk < 16; kk++) {
            const float a0 = xs[st][ty * 4 + 0][kk];
            const float a1 = xs[st][ty * 4 + 1][kk];
            const float a2 = xs[st][ty * 4 + 2][kk];
            const float a3 = xs[st][ty * 4 + 3][kk];
            const float b0 = ws[st][tx * 4 + 0][kk];
            const float b1 = ws[st][tx * 4 + 1][kk];
            const float b2 = ws[st][tx * 4 + 2][kk];
            const float b3 = ws[st][tx * 4 + 3][kk];
            acc[0][0] += a0 * b0;  acc[0][1] += a0 * b1;
            acc[0][2] += a0 * b2;  acc[0][3] += a0 * b3;
            acc[1][0] += a1 * b0;  acc[1][1] += a1 * b1;
            acc[1][2] += a1 * b2;  acc[1][3] += a1 * b3;
            acc[2][0] += a2 * b0;  acc[2][1] += a2 * b1;
            acc[2][2] += a2 * b2;  acc[2][3] += a2 * b3;
            acc[3][0] += a3 * b0;  acc[3][1] += a3 * b1;
            acc[3][2] += a3 * b2;  acc[3][3] += a3 * b3;
        }
        __syncthreads();
    }

    // softmax + argmax per token (16 lanes per token group; width-16 shuffles)
    const unsigned FULL = 0xffffffffu;
    float cadd[4] = {0.0f, 0.0f, 0.0f, 0.0f};

#pragma unroll
    for (int i = 0; i < 4; i++) {
        float m = fmaxf(fmaxf(acc[i][0], acc[i][1]), fmaxf(acc[i][2], acc[i][3]));
#pragma unroll
        for (int d = 8; d >= 1; d >>= 1)
            m = fmaxf(m, __shfl_xor_sync(FULL, m, d, 16));

        float ev0 = __expf(acc[i][0] - m);
        float ev1 = __expf(acc[i][1] - m);
        float ev2 = __expf(acc[i][2] - m);
        float ev3 = __expf(acc[i][3] - m);
        float ssum = ev0 + ev1 + ev2 + ev3;
#pragma unroll
        for (int d = 8; d >= 1; d >>= 1)
            ssum += __shfl_xor_sync(FULL, ssum, d, 16);
        const float rs = 1.0f / ssum;

        cadd[0] += ev0 * rs;  cadd[1] += ev1 * rs;
        cadd[2] += ev2 * rs;  cadd[3] += ev3 * rs;

        // argmax (first occurrence on ties)
        float bv = acc[i][0]; int bidx = tx * 4;
#pragma unroll
        for (int j = 1; j < 4; j++)
            if (acc[i][j] > bv) { bv = acc[i][j]; bidx = tx * 4 + j; }
#pragma unroll
        for (int d = 8; d >= 1; d >>= 1) {
            float ov = __shfl_xor_sync(FULL, bv, d, 16);
            int   oi = __shfl_xor_sync(FULL, bidx, d, 16);
            if (ov > bv || (ov == bv && oi < bidx)) { bv = ov; bidx = oi; }
        }
        if (tx == 0) {
            const int s = sb + ty * 4 + i;
            g_expert[s] = bidx;
            g_gate[s]   = rs;
        }
    }

    // deterministic per-block column sums
#pragma unroll
    for (int j = 0; j < 4; j++) colv[ty][tx * 4 + j] = cadd[j];
    __syncthreads();
    if (tid < 64) {
        float sum = 0.0f;
#pragma unroll
        for (int r = 0; r < 16; r++) sum += colv[r][tid];
        g_partSum[blockIdx.x * 64 + tid] = sum;
    }
}

// ---------------------------------------------------------------------------
// Kernel 2: per-chunk (128 tokens) expert histograms + within-chunk ranks.
// ---------------------------------------------------------------------------
__global__ __launch_bounds__(128) void rank_kernel() {
    __shared__ int whist[4][64];
    const int tid = threadIdx.x;
    const int s   = blockIdx.x * 128 + tid;
    const int e   = g_expert[s];

    ((int*)whist)[tid]       = 0;
    ((int*)whist)[tid + 128] = 0;
    __syncthreads();

    const unsigned mm = __match_any_sync(0xffffffffu, e);
    const int lane = tid & 31;
    const int w    = tid >> 5;
    const int rw   = __popc(mm & ((1u << lane) - 1u));
    if ((int)(__ffs(mm) - 1) == lane) whist[w][e] = __popc(mm);
    __syncthreads();

    int before = 0;
    for (int p = 0; p < w; p++) before += whist[p][e];
    g_rank[s] = rw + before;

    if (tid < 64)
        g_chunkHist[blockIdx.x * 64 + tid] =
            whist[0][tid] + whist[1][tid] + whist[2][tid] + whist[3][tid];
}

// ---------------------------------------------------------------------------
// Kernel 3: exclusive scan of chunk hist per expert + l_aux.
// ---------------------------------------------------------------------------
__global__ __launch_bounds__(64) void scan_kernel(float* __restrict__ out, int has_laux) {
    const int e = threadIdx.x;
    int run = 0;
    for (int b = 0; b < 64; b++) {
        const int h = g_chunkHist[b * 64 + e];
        g_chunkBase[b * 64 + e] = run;
        run += h;
    }
    float gs = 0.0f;
    for (int p = 0; p < GATE_BLOCKS; p++) gs += g_partSum[p * 64 + e];

    float contrib = gs * (float)run;
#pragma unroll
    for (int d = 16; d >= 1; d >>= 1)
        contrib += __shfl_xor_sync(0xffffffffu, contrib, d);

    __shared__ float part[2];
    if ((threadIdx.x & 31) == 0) part[threadIdx.x >> 5] = contrib;
    __syncthreads();
    if (threadIdx.x == 0 && has_laux)
        out[0] = ((float)E / ((float)S * (float)S)) * (part[0] + part[1]);
}

// ---------------------------------------------------------------------------
// Kernel 4: scatter combine_weights + dispatch_mask (only kept tokens).
// ---------------------------------------------------------------------------
__global__ __launch_bounds__(256) void scatter_kernel(float* __restrict__ out,
                                                      long combine_base, int has_mask) {
    const int s = blockIdx.x * 256 + threadIdx.x;
    const int e = g_expert[s];
    const int loc = g_chunkBase[(s >> 7) * 64 + e] + g_rank[s];
    if (loc < CAP) {
        const long idx = combine_base + ((long)s * E + e) * CAP + loc;
        out[idx] = g_gate[s];
        if (has_mask) out[idx + (long)S * E * CAP] = 1.0f;
    }
}

// ---------------------------------------------------------------------------
extern "C" void kernel_launch(void* const* d_in, const int* in_sizes, int n_in,
                              void* d_out, int out_size) {
    const float* x  = (const float*)d_in[0];
    const float* wg = (const float*)d_in[1];
    float* out = (float*)d_out;

    const long SEC = (long)S * E * CAP;                 // 67,108,864
    const int has_mask = ((long)out_size >= 2 * SEC);
    const long cb = (long)out_size - (has_mask ? 2 : 1) * SEC;
    const int has_laux = (cb > 0);

    // Side stream + events (created once, pre-capture; harness runs a
    // correctness call before capturing).
    static cudaStream_t s2 = nullptr;
    static cudaEvent_t evFork = nullptr, evJoin = nullptr;
    if (s2 == nullptr) {
        cudaStreamCreateWithFlags(&s2, cudaStreamNonBlocking);
        cudaEventCreateWithFlags(&evFork, cudaEventDisableTiming);
        cudaEventCreateWithFlags(&evJoin, cudaEventDisableTiming);
    }

    // Fork: 537MB zero-fill concurrent with the (now latency-hardened) gate.
    cudaEventRecord(evFork, 0);
    cudaStreamWaitEvent(s2, evFork, 0);
    cudaMemsetAsync(d_out, 0, (size_t)out_size * sizeof(float), s2);
    cudaEventRecord(evJoin, s2);

    gate_kernel<<<GATE_BLOCKS, 256>>>(x, wg);
    rank_kernel<<<S / 128, 128>>>();

    // Join before anything touches the output buffer.
    cudaStreamWaitEvent(0, evJoin, 0);
    scan_kernel<<<1, 64>>>(out, has_laux);
    scatter_kernel<<<S / 256, 256>>>(out, cb, has_mask);
}

// round 11
// speedup vs baseline: 1.7599x; 1.7599x over previous
#include <cuda_runtime.h>
#include <cstdint>

// Problem constants
#define S   8192
#define Dm  2048
#define E   64
#define CAP 128   // ceil(S/E * 1.0)

#define GATE_BLOCKS (S / 64)   // 128 blocks, one per SM

// ---------------- device scratch (no allocations allowed) ----------------
__device__ int   g_expert[S];
__device__ float g_gate[S];
__device__ int   g_rank[S];
__device__ int   g_chunkHist[64 * 64];
__device__ int   g_chunkBase[64 * 64];
__device__ float g_partSum[GATE_BLOCKS * 64];

// ---------------------------------------------------------------------------
// Kernel 1: logits = x @ wg^T. EXACT R8 mainloop (64 tok x 64 exp, 4x4 reg
// tile, [k][row] smem layout, 2x LDS.128 + 16 FFMA per kk) with the global
// prefetch deepened to TWO register buffers (A/B, loop unrolled by 2):
// each LDG is issued ~2 compute tiles (~2048+ cyc) before its STS consumes
// it, so the loop tolerates DRAM latency inflated by the concurrently
// running 537MB zero-fill. Accumulation order identical to R8.
// ---------------------------------------------------------------------------
__global__ __launch_bounds__(256, 1) void gate_kernel(const float* __restrict__ x,
                                                      const float* __restrict__ wg) {
    __shared__ __align__(16) float xs[16][68];  // [k][token]
    __shared__ __align__(16) float ws[16][68];  // [k][expert]
    __shared__ float colv[16][64];

    const int tid = threadIdx.x;
    const int ty  = tid >> 4;      // 0..15 -> token quad
    const int tx  = tid & 15;      // 0..15 -> expert quad
    const int sb  = blockIdx.x * 64;

    float acc[4][4];
#pragma unroll
    for (int i = 0; i < 4; i++)
#pragma unroll
        for (int j = 0; j < 4; j++) acc[i][j] = 0.0f;

    const int row = tid >> 2;          // token / expert 0..63
    const int kq  = (tid & 3) * 4;     // k offset (float4)

    const float* xrow = x  + (size_t)(sb + row) * Dm + kq;
    const float* wrow = wg + (size_t)row * Dm + kq;

    // depth-2 register prefetch: A = even tiles, B = odd tiles
    float4 xvA = *(const float4*)(xrow);
    float4 wvA = *(const float4*)(wrow);
    float4 xvB = *(const float4*)(xrow + 16);
    float4 wvB = *(const float4*)(wrow + 16);

#define STORE_TILE(xv, wv)                 \
    xs[kq    ][row] = (xv).x;              \
    xs[kq + 1][row] = (xv).y;              \
    xs[kq + 2][row] = (xv).z;              \
    xs[kq + 3][row] = (xv).w;              \
    ws[kq    ][row] = (wv).x;              \
    ws[kq + 1][row] = (wv).y;              \
    ws[kq + 2][row] = (wv).z;              \
    ws[kq + 3][row] = (wv).w;

#define COMPUTE_TILE()                                                  \
    _Pragma("unroll")                                                   \
    for (int kk = 0; kk < 16; kk++) {                                   \
        const float4 a = *(const float4*)&xs[kk][ty * 4];               \
        const float4 b = *(const float4*)&ws[kk][tx * 4];               \
        acc[0][0] += a.x * b.x;  acc[0][1] += a.x * b.y;                \
        acc[0][2] += a.x * b.z;  acc[0][3] += a.x * b.w;                \
        acc[1][0] += a.y * b.x;  acc[1][1] += a.y * b.y;                \
        acc[1][2] += a.y * b.z;  acc[1][3] += a.y * b.w;                \
        acc[2][0] += a.z * b.x;  acc[2][1] += a.z * b.y;                \
        acc[2][2] += a.z * b.z;  acc[2][3] += a.z * b.w;                \
        acc[3][0] += a.w * b.x;  acc[3][1] += a.w * b.y;                \
        acc[3][2] += a.w * b.z;  acc[3][3] += a.w * b.w;                \
    }

    for (int k0 = 0; k0 < Dm; k0 += 32) {
        // even tile (buffer A)
        STORE_TILE(xvA, wvA)
        __syncthreads();
        if (k0 + 32 < Dm) {  // refill A for tile k0+32, consumed 2 tiles later
            xvA = *(const float4*)(xrow + k0 + 32);
            wvA = *(const float4*)(wrow + k0 + 32);
        }
        COMPUTE_TILE()
        __syncthreads();

        // odd tile (buffer B)
        STORE_TILE(xvB, wvB)
        __syncthreads();
        if (k0 + 48 < Dm) {  // refill B for tile k0+48
            xvB = *(const float4*)(xrow + k0 + 48);
            wvB = *(const float4*)(wrow + k0 + 48);
        }
        COMPUTE_TILE()
        __syncthreads();
    }
#undef STORE_TILE
#undef COMPUTE_TILE

    // softmax + argmax per token (16 lanes per token group; width-16 shuffles)
    const unsigned FULL = 0xffffffffu;
    float cadd[4] = {0.0f, 0.0f, 0.0f, 0.0f};

#pragma unroll
    for (int i = 0; i < 4; i++) {
        float m = fmaxf(fmaxf(acc[i][0], acc[i][1]), fmaxf(acc[i][2], acc[i][3]));
#pragma unroll
        for (int d = 8; d >= 1; d >>= 1)
            m = fmaxf(m, __shfl_xor_sync(FULL, m, d, 16));

        float ev0 = __expf(acc[i][0] - m);
        float ev1 = __expf(acc[i][1] - m);
        float ev2 = __expf(acc[i][2] - m);
        float ev3 = __expf(acc[i][3] - m);
        float ssum = ev0 + ev1 + ev2 + ev3;
#pragma unroll
        for (int d = 8; d >= 1; d >>= 1)
            ssum += __shfl_xor_sync(FULL, ssum, d, 16);
        const float rs = 1.0f / ssum;

        cadd[0] += ev0 * rs;  cadd[1] += ev1 * rs;
        cadd[2] += ev2 * rs;  cadd[3] += ev3 * rs;

        // argmax (first occurrence on ties)
        float bv = acc[i][0]; int bidx = tx * 4;
#pragma unroll
        for (int j = 1; j < 4; j++)
            if (acc[i][j] > bv) { bv = acc[i][j]; bidx = tx * 4 + j; }
#pragma unroll
        for (int d = 8; d >= 1; d >>= 1) {
            float ov = __shfl_xor_sync(FULL, bv, d, 16);
            int   oi = __shfl_xor_sync(FULL, bidx, d, 16);
            if (ov > bv || (ov == bv && oi < bidx)) { bv = ov; bidx = oi; }
        }
        if (tx == 0) {
            const int s = sb + ty * 4 + i;
            g_expert[s] = bidx;
            g_gate[s]   = rs;
        }
    }

    // deterministic per-block column sums
#pragma unroll
    for (int j = 0; j < 4; j++) colv[ty][tx * 4 + j] = cadd[j];
    __syncthreads();
    if (tid < 64) {
        float sum = 0.0f;
#pragma unroll
        for (int r = 0; r < 16; r++) sum += colv[r][tid];
        g_partSum[blockIdx.x * 64 + tid] = sum;
    }
}

// ---------------------------------------------------------------------------
// Kernel 2: per-chunk (128 tokens) expert histograms + within-chunk ranks.
// ---------------------------------------------------------------------------
__global__ __launch_bounds__(128) void rank_kernel() {
    __shared__ int whist[4][64];
    const int tid = threadIdx.x;
    const int s   = blockIdx.x * 128 + tid;
    const int e   = g_expert[s];

    ((int*)whist)[tid]       = 0;
    ((int*)whist)[tid + 128] = 0;
    __syncthreads();

    const unsigned mm = __match_any_sync(0xffffffffu, e);
    const int lane = tid & 31;
    const int w    = tid >> 5;
    const int rw   = __popc(mm & ((1u << lane) - 1u));
    if ((int)(__ffs(mm) - 1) == lane) whist[w][e] = __popc(mm);
    __syncthreads();

    int before = 0;
    for (int p = 0; p < w; p++) before += whist[p][e];
    g_rank[s] = rw + before;

    if (tid < 64)
        g_chunkHist[blockIdx.x * 64 + tid] =
            whist[0][tid] + whist[1][tid] + whist[2][tid] + whist[3][tid];
}

// ---------------------------------------------------------------------------
// Kernel 3: exclusive scan of chunk hist per expert + l_aux.
// ---------------------------------------------------------------------------
__global__ __launch_bounds__(64) void scan_kernel(float* __restrict__ out, int has_laux) {
    const int e = threadIdx.x;
    int run = 0;
    for (int b = 0; b < 64; b++) {
        const int h = g_chunkHist[b * 64 + e];
        g_chunkBase[b * 64 + e] = run;
        run += h;
    }
    float gs = 0.0f;
    for (int p = 0; p < GATE_BLOCKS; p++) gs += g_partSum[p * 64 + e];

    float contrib = gs * (float)run;
#pragma unroll
    for (int d = 16; d >= 1; d >>= 1)
        contrib += __shfl_xor_sync(0xffffffffu, contrib, d);

    __shared__ float part[2];
    if ((threadIdx.x & 31) == 0) part[threadIdx.x >> 5] = contrib;
    __syncthreads();
    if (threadIdx.x == 0 && has_laux)
        out[0] = ((float)E / ((float)S * (float)S)) * (part[0] + part[1]);
}

// ---------------------------------------------------------------------------
// Kernel 4: scatter combine_weights + dispatch_mask (only kept tokens).
// ---------------------------------------------------------------------------
__global__ __launch_bounds__(256) void scatter_kernel(float* __restrict__ out,
                                                      long combine_base, int has_mask) {
    const int s = blockIdx.x * 256 + threadIdx.x;
    const int e = g_expert[s];
    const int loc = g_chunkBase[(s >> 7) * 64 + e] + g_rank[s];
    if (loc < CAP) {
        const long idx = combine_base + ((long)s * E + e) * CAP + loc;
        out[idx] = g_gate[s];
        if (has_mask) out[idx + (long)S * E * CAP] = 1.0f;
    }
}

// ---------------------------------------------------------------------------
extern "C" void kernel_launch(void* const* d_in, const int* in_sizes, int n_in,
                              void* d_out, int out_size) {
    const float* x  = (const float*)d_in[0];
    const float* wg = (const float*)d_in[1];
    float* out = (float*)d_out;

    const long SEC = (long)S * E * CAP;                 // 67,108,864
    const int has_mask = ((long)out_size >= 2 * SEC);
    const long cb = (long)out_size - (has_mask ? 2 : 1) * SEC;
    const int has_laux = (cb > 0);

    // Side stream + events (created once, pre-capture; harness runs a
    // correctness call before capturing).
    static cudaStream_t s2 = nullptr;
    static cudaEvent_t evFork = nullptr, evJoin = nullptr;
    if (s2 == nullptr) {
        cudaStreamCreateWithFlags(&s2, cudaStreamNonBlocking);
        cudaEventCreateWithFlags(&evFork, cudaEventDisableTiming);
        cudaEventCreateWithFlags(&evJoin, cudaEventDisableTiming);
    }

    // Fork: 537MB zero-fill concurrent with the latency-hardened gate.
    cudaEventRecord(evFork, 0);
    cudaStreamWaitEvent(s2, evFork, 0);
    cudaMemsetAsync(d_out, 0, (size_t)out_size * sizeof(float), s2);
    cudaEventRecord(evJoin, s2);

    gate_kernel<<<GATE_BLOCKS, 256>>>(x, wg);
    rank_kernel<<<S / 128, 128>>>();   // no d_out dependence; overlaps memset tail

    // Join before anything touches the output buffer.
    cudaStreamWaitEvent(0, evJoin, 0);
    scan_kernel<<<1, 64>>>(out, has_laux);
    scatter_kernel<<<S / 256, 256>>>(out, cb, has_mask);
}

// round 12
// speedup vs baseline: 3.1776x; 1.8055x over previous
#include <cuda_runtime.h>
#include <cstdint>

// Problem constants
#define S   8192
#define Dm  2048
#define E   64
#define CAP 128   // ceil(S/E * 1.0)

#define GATE_BLOCKS (S / 64)   // 128 blocks, one per SM

// ---------------- device scratch (no allocations allowed) ----------------
__device__ int   g_expert[S];
__device__ float g_gate[S];
__device__ int   g_rank[S];
__device__ int   g_chunkHist[64 * 64];
__device__ int   g_chunkBase[64 * 64];
__device__ float g_partSum[GATE_BLOCKS * 64];

// ---------------------------------------------------------------------------
// Kernel 1: logits = x @ wg^T. R8 mainloop (64 tok x 64 exp, 4x4 reg tile,
// [k][row] smem, 2x LDS.128 + 16 FFMA per kk) with DOUBLE-BUFFERED smem:
// iteration t stores tile t+1 into buf[(t+1)&1] while computing buf[t&1],
// so only ONE __syncthreads per k-tile and the store phase overlaps compute.
// Serial memset (R3/R10/R11 proved overlap with the 537MB fill always loses).
// ---------------------------------------------------------------------------
__global__ __launch_bounds__(256, 1) void gate_kernel(const float* __restrict__ x,
                                                      const float* __restrict__ wg) {
    __shared__ __align__(16) float xs[2][16][68];  // [buf][k][token]
    __shared__ __align__(16) float ws[2][16][68];  // [buf][k][expert]
    __shared__ float colv[16][64];

    const int tid = threadIdx.x;
    const int ty  = tid >> 4;      // 0..15 -> token quad
    const int tx  = tid & 15;      // 0..15 -> expert quad
    const int sb  = blockIdx.x * 64;

    float acc[4][4];
#pragma unroll
    for (int i = 0; i < 4; i++)
#pragma unroll
        for (int j = 0; j < 4; j++) acc[i][j] = 0.0f;

    const int row = tid >> 2;          // token / expert 0..63
    const int kq  = (tid & 3) * 4;     // k offset (float4)

    const float* xrow = x  + (size_t)(sb + row) * Dm + kq;
    const float* wrow = wg + (size_t)row * Dm + kq;

    const int NT = Dm / 16;  // 128 k-tiles

    // prologue: tile 0 into buf0, prefetch tile 1 into regs
    float4 xv = *(const float4*)(xrow);
    float4 wv = *(const float4*)(wrow);
    xs[0][kq    ][row] = xv.x;  xs[0][kq + 1][row] = xv.y;
    xs[0][kq + 2][row] = xv.z;  xs[0][kq + 3][row] = xv.w;
    ws[0][kq    ][row] = wv.x;  ws[0][kq + 1][row] = wv.y;
    ws[0][kq + 2][row] = wv.z;  ws[0][kq + 3][row] = wv.w;
    xv = *(const float4*)(xrow + 16);
    wv = *(const float4*)(wrow + 16);
    __syncthreads();

    for (int t = 0; t < NT; t++) {
        const int cb = t & 1;        // compute buffer
        const int sbuf = cb ^ 1;     // store buffer (tile t+1)

        if (t + 1 < NT) {            // store prefetched tile t+1
            xs[sbuf][kq    ][row] = xv.x;  xs[sbuf][kq + 1][row] = xv.y;
            xs[sbuf][kq + 2][row] = xv.z;  xs[sbuf][kq + 3][row] = xv.w;
            ws[sbuf][kq    ][row] = wv.x;  ws[sbuf][kq + 1][row] = wv.y;
            ws[sbuf][kq + 2][row] = wv.z;  ws[sbuf][kq + 3][row] = wv.w;
        }
        if (t + 2 < NT) {            // prefetch tile t+2
            xv = *(const float4*)(xrow + (t + 2) * 16);
            wv = *(const float4*)(wrow + (t + 2) * 16);
        }

#pragma unroll
        for (int kk = 0; kk < 16; kk++) {
            const float4 a = *(const float4*)&xs[cb][kk][ty * 4];
            const float4 b = *(const float4*)&ws[cb][kk][tx * 4];
            acc[0][0] += a.x * b.x;  acc[0][1] += a.x * b.y;
            acc[0][2] += a.x * b.z;  acc[0][3] += a.x * b.w;
            acc[1][0] += a.y * b.x;  acc[1][1] += a.y * b.y;
            acc[1][2] += a.y * b.z;  acc[1][3] += a.y * b.w;
            acc[2][0] += a.z * b.x;  acc[2][1] += a.z * b.y;
            acc[2][2] += a.z * b.z;  acc[2][3] += a.z * b.w;
            acc[3][0] += a.w * b.x;  acc[3][1] += a.w * b.y;
            acc[3][2] += a.w * b.z;  acc[3][3] += a.w * b.w;
        }
        __syncthreads();   // single barrier per tile
    }

    // softmax + argmax per token (16 lanes per token group; width-16 shuffles)
    const unsigned FULL = 0xffffffffu;
    float cadd[4] = {0.0f, 0.0f, 0.0f, 0.0f};

#pragma unroll
    for (int i = 0; i < 4; i++) {
        float m = fmaxf(fmaxf(acc[i][0], acc[i][1]), fmaxf(acc[i][2], acc[i][3]));
#pragma unroll
        for (int d = 8; d >= 1; d >>= 1)
            m = fmaxf(m, __shfl_xor_sync(FULL, m, d, 16));

        float ev0 = __expf(acc[i][0] - m);
        float ev1 = __expf(acc[i][1] - m);
        float ev2 = __expf(acc[i][2] - m);
        float ev3 = __expf(acc[i][3] - m);
        float ssum = ev0 + ev1 + ev2 + ev3;
#pragma unroll
        for (int d = 8; d >= 1; d >>= 1)
            ssum += __shfl_xor_sync(FULL, ssum, d, 16);
        const float rs = 1.0f / ssum;

        cadd[0] += ev0 * rs;  cadd[1] += ev1 * rs;
        cadd[2] += ev2 * rs;  cadd[3] += ev3 * rs;

        // argmax (first occurrence on ties)
        float bv = acc[i][0]; int bidx = tx * 4;
#pragma unroll
        for (int j = 1; j < 4; j++)
            if (acc[i][j] > bv) { bv = acc[i][j]; bidx = tx * 4 + j; }
#pragma unroll
        for (int d = 8; d >= 1; d >>= 1) {
            float ov = __shfl_xor_sync(FULL, bv, d, 16);
            int   oi = __shfl_xor_sync(FULL, bidx, d, 16);
            if (ov > bv || (ov == bv && oi < bidx)) { bv = ov; bidx = oi; }
        }
        if (tx == 0) {
            const int s = sb + ty * 4 + i;
            g_expert[s] = bidx;
            g_gate[s]   = rs;
        }
    }

    // deterministic per-block column sums
#pragma unroll
    for (int j = 0; j < 4; j++) colv[ty][tx * 4 + j] = cadd[j];
    __syncthreads();
    if (tid < 64) {
        float sum = 0.0f;
#pragma unroll
        for (int r = 0; r < 16; r++) sum += colv[r][tid];
        g_partSum[blockIdx.x * 64 + tid] = sum;
    }
}

// ---------------------------------------------------------------------------
// Kernel 2: per-chunk (128 tokens) expert histograms + within-chunk ranks.
// ---------------------------------------------------------------------------
__global__ __launch_bounds__(128) void rank_kernel() {
    __shared__ int whist[4][64];
    const int tid = threadIdx.x;
    const int s   = blockIdx.x * 128 + tid;
    const int e   = g_expert[s];

    ((int*)whist)[tid]       = 0;
    ((int*)whist)[tid + 128] = 0;
    __syncthreads();

    const unsigned mm = __match_any_sync(0xffffffffu, e);
    const int lane = tid & 31;
    const int w    = tid >> 5;
    const int rw   = __popc(mm & ((1u << lane) - 1u));
    if ((int)(__ffs(mm) - 1) == lane) whist[w][e] = __popc(mm);
    __syncthreads();

    int before = 0;
    for (int p = 0; p < w; p++) before += whist[p][e];
    g_rank[s] = rw + before;

    if (tid < 64)
        g_chunkHist[blockIdx.x * 64 + tid] =
            whist[0][tid] + whist[1][tid] + whist[2][tid] + whist[3][tid];
}

// ---------------------------------------------------------------------------
// Kernel 3: exclusive scan of chunk hist per expert + l_aux.
// ---------------------------------------------------------------------------
__global__ __launch_bounds__(64) void scan_kernel(float* __restrict__ out, int has_laux) {
    const int e = threadIdx.x;
    int run = 0;
    for (int b = 0; b < 64; b++) {
        const int h = g_chunkHist[b * 64 + e];
        g_chunkBase[b * 64 + e] = run;
        run += h;
    }
    float gs = 0.0f;
    for (int p = 0; p < GATE_BLOCKS; p++) gs += g_partSum[p * 64 + e];

    float contrib = gs * (float)run;
#pragma unroll
    for (int d = 16; d >= 1; d >>= 1)
        contrib += __shfl_xor_sync(0xffffffffu, contrib, d);

    __shared__ float part[2];
    if ((threadIdx.x & 31) == 0) part[threadIdx.x >> 5] = contrib;
    __syncthreads();
    if (threadIdx.x == 0 && has_laux)
        out[0] = ((float)E / ((float)S * (float)S)) * (part[0] + part[1]);
}

// ---------------------------------------------------------------------------
// Kernel 4: scatter combine_weights + dispatch_mask (only kept tokens).
// ---------------------------------------------------------------------------
__global__ __launch_bounds__(256) void scatter_kernel(float* __restrict__ out,
                                                      long combine_base, int has_mask) {
    const int s = blockIdx.x * 256 + threadIdx.x;
    const int e = g_expert[s];
    const int loc = g_chunkBase[(s >> 7) * 64 + e] + g_rank[s];
    if (loc < CAP) {
        const long idx = combine_base + ((long)s * E + e) * CAP + loc;
        out[idx] = g_gate[s];
        if (has_mask) out[idx + (long)S * E * CAP] = 1.0f;
    }
}

// ---------------------------------------------------------------------------
extern "C" void kernel_launch(void* const* d_in, const int* in_sizes, int n_in,
                              void* d_out, int out_size) {
    const float* x  = (const float*)d_in[0];
    const float* wg = (const float*)d_in[1];
    float* out = (float*)d_out;

    const long SEC = (long)S * E * CAP;                 // 67,108,864
    const int has_mask = ((long)out_size >= 2 * SEC);
    const long cb = (long)out_size - (has_mask ? 2 : 1) * SEC;
    const int has_laux = (cb > 0);

    // zero-fill entire output, serial (overlap with the GEMM loses — proven
    // three times: R3, R10, R11)
    cudaMemsetAsync(d_out, 0, (size_t)out_size * sizeof(float), 0);

    gate_kernel<<<GATE_BLOCKS, 256>>>(x, wg);
    rank_kernel<<<S / 128, 128>>>();
    scan_kernel<<<1, 64>>>(out, has_laux);
    scatter_kernel<<<S / 256, 256>>>(out, cb, has_mask);
}

// round 14
// speedup vs baseline: 3.4302x; 1.0795x over previous
#include <cuda_runtime.h>
#include <cstdint>

// Problem constants
#define S   8192
#define Dm  2048
#define E   64
#define CAP 128   // ceil(S/E * 1.0)

#define GATE_BLOCKS (S / 64)   // 128 blocks, one per SM; chunk == block == 64 tokens

// ---------------- device scratch (no allocations allowed) ----------------
__device__ int   g_expert[S];
__device__ float g_gate[S];
__device__ int   g_rank[S];                      // rank within 64-token chunk
__device__ int   g_chunkHist[GATE_BLOCKS * 64];  // [chunk][expert]
__device__ int   g_chunkBase[GATE_BLOCKS * 64];  // exclusive prefix over chunks
__device__ float g_partSum[GATE_BLOCKS * 64];    // per-block gate column sums
__device__ float g_laux;                         // l_aux staging (out[0] written by scatter)

// ---------------------------------------------------------------------------
// Kernel 1: logits = x @ wg^T (R12 double-buffered mainloop, unchanged), then
// softmax/argmax/gate, per-block column sums, AND fused per-chunk (=per-block,
// 64 tokens) expert histogram + within-chunk ranks (was rank_kernel).
// ---------------------------------------------------------------------------
__global__ __launch_bounds__(256, 1) void gate_kernel(const float* __restrict__ x,
                                                      const float* __restrict__ wg) {
    __shared__ __align__(16) float xs[2][16][68];  // [buf][k][token]
    __shared__ __align__(16) float ws[2][16][68];  // [buf][k][expert]
    __shared__ float colv[16][64];
    __shared__ int   sexp[64];
    __shared__ int   whist[2][64];

    const int tid = threadIdx.x;
    const int ty  = tid >> 4;      // 0..15 -> token quad
    const int tx  = tid & 15;      // 0..15 -> expert quad
    const int sb  = blockIdx.x * 64;

    float acc[4][4];
#pragma unroll
    for (int i = 0; i < 4; i++)
#pragma unroll
        for (int j = 0; j < 4; j++) acc[i][j] = 0.0f;

    const int row = tid >> 2;          // token / expert 0..63
    const int kq  = (tid & 3) * 4;     // k offset (float4)

    const float* xrow = x  + (size_t)(sb + row) * Dm + kq;
    const float* wrow = wg + (size_t)row * Dm + kq;

    const int NT = Dm / 16;  // 128 k-tiles

    // prologue: tile 0 into buf0, prefetch tile 1 into regs
    float4 xv = *(const float4*)(xrow);
    float4 wv = *(const float4*)(wrow);
    xs[0][kq    ][row] = xv.x;  xs[0][kq + 1][row] = xv.y;
    xs[0][kq + 2][row] = xv.z;  xs[0][kq + 3][row] = xv.w;
    ws[0][kq    ][row] = wv.x;  ws[0][kq + 1][row] = wv.y;
    ws[0][kq + 2][row] = wv.z;  ws[0][kq + 3][row] = wv.w;
    xv = *(const float4*)(xrow + 16);
    wv = *(const float4*)(wrow + 16);
    __syncthreads();

    for (int t = 0; t < NT; t++) {
        const int cb = t & 1;        // compute buffer
        const int sbuf = cb ^ 1;     // store buffer (tile t+1)

        if (t + 1 < NT) {            // store prefetched tile t+1
            xs[sbuf][kq    ][row] = xv.x;  xs[sbuf][kq + 1][row] = xv.y;
            xs[sbuf][kq + 2][row] = xv.z;  xs[sbuf][kq + 3][row] = xv.w;
            ws[sbuf][kq    ][row] = wv.x;  ws[sbuf][kq + 1][row] = wv.y;
            ws[sbuf][kq + 2][row] = wv.z;  ws[sbuf][kq + 3][row] = wv.w;
        }
        if (t + 2 < NT) {            // prefetch tile t+2
            xv = *(const float4*)(xrow + (t + 2) * 16);
            wv = *(const float4*)(wrow + (t + 2) * 16);
        }

#pragma unroll
        for (int kk = 0; kk < 16; kk++) {
            const float4 a = *(const float4*)&xs[cb][kk][ty * 4];
            const float4 b = *(const float4*)&ws[cb][kk][tx * 4];
            acc[0][0] += a.x * b.x;  acc[0][1] += a.x * b.y;
            acc[0][2] += a.x * b.z;  acc[0][3] += a.x * b.w;
            acc[1][0] += a.y * b.x;  acc[1][1] += a.y * b.y;
            acc[1][2] += a.y * b.z;  acc[1][3] += a.y * b.w;
            acc[2][0] += a.z * b.x;  acc[2][1] += a.z * b.y;
            acc[2][2] += a.z * b.z;  acc[2][3] += a.z * b.w;
            acc[3][0] += a.w * b.x;  acc[3][1] += a.w * b.y;
            acc[3][2] += a.w * b.z;  acc[3][3] += a.w * b.w;
        }
        __syncthreads();   // single barrier per tile
    }

    // softmax + argmax per token (16 lanes per token group; width-16 shuffles)
    const unsigned FULL = 0xffffffffu;
    float cadd[4] = {0.0f, 0.0f, 0.0f, 0.0f};

#pragma unroll
    for (int i = 0; i < 4; i++) {
        float m = fmaxf(fmaxf(acc[i][0], acc[i][1]), fmaxf(acc[i][2], acc[i][3]));
#pragma unroll
        for (int d = 8; d >= 1; d >>= 1)
            m = fmaxf(m, __shfl_xor_sync(FULL, m, d, 16));

        float ev0 = __expf(acc[i][0] - m);
        float ev1 = __expf(acc[i][1] - m);
        float ev2 = __expf(acc[i][2] - m);
        float ev3 = __expf(acc[i][3] - m);
        float ssum = ev0 + ev1 + ev2 + ev3;
#pragma unroll
        for (int d = 8; d >= 1; d >>= 1)
            ssum += __shfl_xor_sync(FULL, ssum, d, 16);
        const float rs = 1.0f / ssum;

        cadd[0] += ev0 * rs;  cadd[1] += ev1 * rs;
        cadd[2] += ev2 * rs;  cadd[3] += ev3 * rs;

        // argmax (first occurrence on ties)
        float bv = acc[i][0]; int bidx = tx * 4;
#pragma unroll
        for (int j = 1; j < 4; j++)
            if (acc[i][j] > bv) { bv = acc[i][j]; bidx = tx * 4 + j; }
#pragma unroll
        for (int d = 8; d >= 1; d >>= 1) {
            float ov = __shfl_xor_sync(FULL, bv, d, 16);
            int   oi = __shfl_xor_sync(FULL, bidx, d, 16);
            if (ov > bv || (ov == bv && oi < bidx)) { bv = ov; bidx = oi; }
        }
        if (tx == 0) {
            const int s = sb + ty * 4 + i;
            g_expert[s] = bidx;
            g_gate[s]   = rs;
            sexp[ty * 4 + i] = bidx;
        }
    }

    // per-block column sums + fused rank computation
#pragma unroll
    for (int j = 0; j < 4; j++) colv[ty][tx * 4 + j] = cadd[j];
    if (tid < 128) ((int*)whist)[tid] = 0;
    __syncthreads();

    if (tid < 64) {
        float sum = 0.0f;
#pragma unroll
        for (int r = 0; r < 16; r++) sum += colv[r][tid];
        g_partSum[blockIdx.x * 64 + tid] = sum;
    }

    int rnk_e = 0; int rnk_rw = 0;
    if (tid < 64) {   // warps 0,1 fully active -> full-mask match_any is valid
        rnk_e = sexp[tid];
        const unsigned mm = __match_any_sync(FULL, rnk_e);
        const int lane = tid & 31;
        rnk_rw = __popc(mm & ((1u << lane) - 1u));
        if ((int)(__ffs(mm) - 1) == lane) whist[tid >> 5][rnk_e] = __popc(mm);
    }
    __syncthreads();
    if (tid < 64) {
        const int before = (tid >= 32) ? whist[0][rnk_e] : 0;
        g_rank[sb + tid] = rnk_rw + before;
        g_chunkHist[blockIdx.x * 64 + tid] = whist[0][tid] + whist[1][tid];
    }
}

// ---------------------------------------------------------------------------
// Kernel 2: exclusive scan of chunk hist per expert + l_aux (to g_laux).
// Runs on a side stream concurrent with the big memset (touches no d_out).
// ---------------------------------------------------------------------------
__global__ __launch_bounds__(64) void scan_kernel() {
    const int e = threadIdx.x;
    int run = 0;
    for (int b = 0; b < GATE_BLOCKS; b++) {
        const int h = g_chunkHist[b * 64 + e];
        g_chunkBase[b * 64 + e] = run;
        run += h;
    }
    float gs = 0.0f;
    for (int p = 0; p < GATE_BLOCKS; p++) gs += g_partSum[p * 64 + e];

    float contrib = gs * (float)run;
#pragma unroll
    for (int d = 16; d >= 1; d >>= 1)
        contrib += __shfl_xor_sync(0xffffffffu, contrib, d);

    __shared__ float part[2];
    if ((threadIdx.x & 31) == 0) part[threadIdx.x >> 5] = contrib;
    __syncthreads();
    if (threadIdx.x == 0)
        g_laux = ((float)E / ((float)S * (float)S)) * (part[0] + part[1]);
}

// ---------------------------------------------------------------------------
// Kernel 3: scatter combine_weights + dispatch_mask; thread (0,0) writes l_aux.
// ---------------------------------------------------------------------------
__global__ __launch_bounds__(256) void scatter_kernel(float* __restrict__ out,
                                                      long combine_base, int has_mask,
                                                      int has_laux) {
    const int s = blockIdx.x * 256 + threadIdx.x;
    if (s == 0 && has_laux) out[0] = g_laux;
    const int e = g_expert[s];
    const int loc = g_chunkBase[(s >> 6) * 64 + e] + g_rank[s];
    if (loc < CAP) {
        const long idx = combine_base + ((long)s * E + e) * CAP + loc;
        out[idx] = g_gate[s];
        if (has_mask) out[idx + (long)S * E * CAP] = 1.0f;
    }
}

// ---------------------------------------------------------------------------
extern "C" void kernel_launch(void* const* d_in, const int* in_sizes, int n_in,
                              void* d_out, int out_size) {
    const float* x  = (const float*)d_in[0];
    const float* wg = (const float*)d_in[1];
    float* out = (float*)d_out;

    const long SEC = (long)S * E * CAP;                 // 67,108,864
    const int has_mask = ((long)out_size >= 2 * SEC);
    const long cb = (long)out_size - (has_mask ? 2 : 1) * SEC;
    const int has_laux = (cb > 0);

    static cudaStream_t s2 = nullptr;
    static cudaEvent_t evFork = nullptr, evJoin = nullptr;
    if (s2 == nullptr) {
        cudaStreamCreateWithFlags(&s2, cudaStreamNonBlocking);
        cudaEventCreateWithFlags(&evFork, cudaEventDisableTiming);
        cudaEventCreateWithFlags(&evJoin, cudaEventDisableTiming);
    }

    // gate first (doesn't touch d_out); it also computes ranks (fused).
    gate_kernel<<<GATE_BLOCKS, 256>>>(x, wg);

    // fork: tiny scan on side stream, 537MB memset on main stream (scan
    // touches no d_out, negligible BW -> safe concurrency; the FAILED
    // overlaps R3/R10/R11 were memset-vs-GATE, not memset-vs-scan).
    cudaEventRecord(evFork, 0);
    cudaStreamWaitEvent(s2, evFork, 0);
    scan_kernel<<<1, 64, 0, s2>>>();
    cudaEventRecord(evJoin, s2);

    cudaMemsetAsync(d_out, 0, (size_t)out_size * sizeof(float), 0);

    cudaStreamWaitEvent(0, evJoin, 0);
    scatter_kernel<<<S / 256, 256>>>(out, cb, has_mask, has_laux);
}